// round 10
// baseline (speedup 1.0000x reference)
#include <cuda_runtime.h>
#include <cuda_bf16.h>

#define BB 2
#define NN 16384
#define PP 4096
#define CC 64
#define SS 32
#define CH (3 + CC)   // 67
#define GC 10
#define NCELL (GC*GC*GC)
#define HB 320        // per-warp hit buffer capacity (multiple of 4)

// ---- scratch (__device__ globals; no cudaMalloc allowed) ----
// g_cnt is zero at module load; scatter's atomicSub countdown restores it to
// zero every launch -> graph replays deterministically with no zeroing pass.
__device__ float4 g_xyz4[BB * NN];           // packed xyz, .w = cell id
__device__ float  g_ftrt[BB * NN * CC];      // features transposed to (B,N,C)
__device__ float4 g_pts [BB * NN];           // cell-sorted points, .w = idx
__device__ int    g_cnt [BB * NCELL];        // counts (self-restoring)
__device__ int    g_start[BB * (NCELL + 1)]; // exclusive scan
__device__ int    g_idx [BB * PP * SS];      // ball query result

__device__ __forceinline__ int cell_of(float x, float y, float z) {
    int cx = min((int)(x * 10.0f), GC - 1);
    int cy = min((int)(y * 10.0f), GC - 1);
    int cz = min((int)(z * 10.0f), GC - 1);
    return (cz * GC + cy) * GC + cx;
}

// ---------------------------------------------------------------------------
// Pack xyz -> float4 (+cell in .w) and histogram cells. 4 points/thread.
// ---------------------------------------------------------------------------
__global__ void pack_count_kernel(const float* __restrict__ xyz) {
    int t  = blockIdx.x * blockDim.x + threadIdx.x;
    int i0 = t * 4;
    if (i0 >= BB * NN) return;
    const float4* src = (const float4*)(xyz + (size_t)i0 * 3);
    float4 a = src[0], b4 = src[1], c4 = src[2];
    float px[4] = {a.x, a.w,  b4.z, c4.y};
    float py[4] = {a.y, b4.x, b4.w, c4.z};
    float pz[4] = {a.z, b4.y, c4.x, c4.w};
    int b = i0 / NN;
#pragma unroll
    for (int k = 0; k < 4; k++) {
        int cell = cell_of(px[k], py[k], pz[k]);
        g_xyz4[i0 + k] = make_float4(px[k], py[k], pz[k], __int_as_float(cell));
        atomicAdd(&g_cnt[b * NCELL + cell], 1);
    }
}

// ---------------------------------------------------------------------------
// Exclusive scan of 1000 counts; one block per batch; leaves g_cnt intact.
// ---------------------------------------------------------------------------
__global__ void scan_kernel() {
    __shared__ int wsum[32];
    int b = blockIdx.x;
    int t = threadIdx.x, lane = t & 31, wid = t >> 5;
    int v = (t < NCELL) ? g_cnt[b * NCELL + t] : 0;
    int s = v;
#pragma unroll
    for (int o = 1; o < 32; o <<= 1) {
        int u = __shfl_up_sync(0xffffffffu, s, o);
        if (lane >= o) s += u;
    }
    if (lane == 31) wsum[wid] = s;
    __syncthreads();
    if (wid == 0) {
        int ws = wsum[lane];
#pragma unroll
        for (int o = 1; o < 32; o <<= 1) {
            int u = __shfl_up_sync(0xffffffffu, ws, o);
            if (lane >= o) ws += u;
        }
        wsum[lane] = ws;
    }
    __syncthreads();
    int incl = s + (wid ? wsum[wid - 1] : 0);
    if (t < NCELL) g_start[b * (NCELL + 1) + t + 1] = incl;
    if (t == 0)    g_start[b * (NCELL + 1)] = 0;
}

// ---------------------------------------------------------------------------
// Scatter into cell-sorted order; countdown atomics restore g_cnt to zero.
// ---------------------------------------------------------------------------
__global__ void scatter_kernel() {
    int i = blockIdx.x * blockDim.x + threadIdx.x;
    if (i >= BB * NN) return;
    int b = i / NN;
    float4 p = g_xyz4[i];
    int c   = __float_as_int(p.w);
    int off = atomicSub(&g_cnt[b * NCELL + c], 1) - 1;
    int pos = g_start[b * (NCELL + 1) + c] + off;
    g_pts[b * NN + pos] = make_float4(p.x, p.y, p.z, __int_as_float(i - b * NN));
}

// ---------------------------------------------------------------------------
// Fused: grid ball query (compute-bound) + feature transpose (memory-bound).
// Query: per-row x-pruned cell scan (conservative over-include; exact frozen
// distance test decides). Rank: all-pairs vs buffer, int4 LDS.128 loads,
// all of a lane's ranks in ONE pass (warp-uniform K variants).
// ---------------------------------------------------------------------------
#define QBLK ((BB * PP) / 8)                // 1024 query blocks
#define TBLK ((NN / 32) * (CC / 32) * BB)   // 2048 transpose blocks

__global__ void __launch_bounds__(256) query_transpose_kernel(
        const float* __restrict__ new_xyz, const float* __restrict__ f) {
    __shared__ union {
        int   hb[8][HB];            // query: per-warp hit buffers
        float tile[32][33];         // transpose tile
    } sm;

    int bx = blockIdx.x;
    if (bx >= QBLK) {
        // ---- transpose part: 32ch x 32pts tile, fully vectorized ----
        int r  = bx - QBLK;
        int nt = NN / 32;
        int b  = r / (nt * 2);
        int rr = r % (nt * 2);
        int c0 = (rr / nt) * 32;
        int n0 = (rr % nt) * 32;
        int t  = threadIdx.x;
        {
            int c = t >> 3, n4 = t & 7;
            float4 v = *(const float4*)(f + ((size_t)b * CC + c0 + c) * NN
                                          + n0 + n4 * 4);
            sm.tile[c][n4 * 4 + 0] = v.x;
            sm.tile[c][n4 * 4 + 1] = v.y;
            sm.tile[c][n4 * 4 + 2] = v.z;
            sm.tile[c][n4 * 4 + 3] = v.w;
        }
        __syncthreads();
        {
            int n = t >> 3, c4 = t & 7;
            float4 v;
            v.x = sm.tile[c4 * 4 + 0][n];
            v.y = sm.tile[c4 * 4 + 1][n];
            v.z = sm.tile[c4 * 4 + 2][n];
            v.w = sm.tile[c4 * 4 + 3][n];
            *(float4*)(g_ftrt + ((size_t)b * NN + n0 + n) * CC + c0 + c4 * 4) = v;
        }
        return;
    }

    // ---- query part ----
    int w    = (bx * blockDim.x + threadIdx.x) >> 5;
    int lane = threadIdx.x & 31;
    int b = w / PP;
    int* buf = sm.hb[(threadIdx.x >> 5) & 7];

    float qx = new_xyz[3 * w + 0];
    float qy = new_xyz[3 * w + 1];
    float qz = new_xyz[3 * w + 2];
    int cx = min((int)(qx * 10.0f), GC - 1);
    int cy = min((int)(qy * 10.0f), GC - 1);
    int cz = min((int)(qz * 10.0f), GC - 1);

    const int*    st  = g_start + b * (NCELL + 1);
    const float4* pts = g_pts + (size_t)b * NN;

    int K = 0;
#pragma unroll
    for (int dz = -1; dz <= 1; dz++) {
        int z = cz + dz;
        if (z < 0 || z >= GC) continue;
        float dzf = (dz == 0) ? 0.0f
                  : (dz < 0 ? qz - (float)cz * 0.1f
                            : (float)(cz + 1) * 0.1f - qz);
        float dz2 = dzf * dzf;
#pragma unroll
        for (int dy = -1; dy <= 1; dy++) {
            int y = cy + dy;
            if (y < 0 || y >= GC) continue;
            float dyf = (dy == 0) ? 0.0f
                      : (dy < 0 ? qy - (float)cy * 0.1f
                                : (float)(cy + 1) * 0.1f - qy);
            float rem = 0.01f + 3e-8f - dz2 - dyf * dyf;
            if (rem <= 0.0f) continue;                 // row can't reach ball
            float dxm = __fsqrt_ru(rem);
            int x0 = max((int)((qx - dxm) * 10.0f - 1e-5f), 0);
            int x1 = min((int)((qx + dxm) * 10.0f + 1e-5f), GC - 1);
            int row = (z * GC + y) * GC;
            int rs = st[row + x0];
            int re = st[row + x1 + 1];
            for (int base = rs; base < re; base += 32) {
                int j = base + lane;
                bool hit = false; int id = 0;
                if (j < re) {
                    float4 pt = pts[j];
                    float ddx = qx - pt.x, ddy = qy - pt.y, ddz = qz - pt.z;
                    float d2 = __fmaf_rn(ddz, ddz,
                               __fmaf_rn(ddy, ddy, __fmul_rn(ddx, ddx)));
                    hit = d2 < 0.01f;
                    id  = __float_as_int(pt.w);
                }
                unsigned m = __ballot_sync(0xffffffffu, hit);
                if (hit) {
                    int pos = K + __popc(m & ((1u << lane) - 1u));
                    if (pos < HB) buf[pos] = id;
                }
                K += __popc(m);
            }
        }
    }
    if (K > HB) K = HB;
    int K4 = (K + 3) & ~3;
    if (lane < K4 - K) buf[K + lane] = 0x7fffffff;     // pad (never "smaller")
    __syncwarp();

    int* out = g_idx + (size_t)w * SS;
    int cnt  = min(K, SS);
    int padv = 0x7fffffff;
    const int4* buf4 = (const int4*)buf;
    int nq = K4 >> 2;

    // Rank = #{u: buf[u] < v}; deterministic (values only). One pass per warp.
    if (K <= 32) {
        int v0 = (lane < K) ? buf[lane] : 0x7fffffff;
        int r0 = 0;
        for (int u = 0; u < nq; u++) {
            int4 q = buf4[u];
            r0 += (q.x < v0) + (q.y < v0) + (q.z < v0) + (q.w < v0);
        }
        if (lane < K && r0 < SS) out[r0] = v0;
        padv = v0;
    } else if (K <= 64) {
        int v0 = buf[lane];
        int v1 = (32 + lane < K) ? buf[32 + lane] : 0x7fffffff;
        int r0 = 0, r1 = 0;
        for (int u = 0; u < nq; u++) {
            int4 q = buf4[u];
            r0 += (q.x < v0) + (q.y < v0) + (q.z < v0) + (q.w < v0);
            r1 += (q.x < v1) + (q.y < v1) + (q.z < v1) + (q.w < v1);
        }
        if (r0 < SS) out[r0] = v0;
        if (32 + lane < K && r1 < SS) out[r1] = v1;
        padv = min(v0, v1);
    } else if (K <= 96) {
        int v0 = buf[lane];
        int v1 = buf[32 + lane];
        int v2 = (64 + lane < K) ? buf[64 + lane] : 0x7fffffff;
        int r0 = 0, r1 = 0, r2 = 0;
        for (int u = 0; u < nq; u++) {
            int4 q = buf4[u];
            r0 += (q.x < v0) + (q.y < v0) + (q.z < v0) + (q.w < v0);
            r1 += (q.x < v1) + (q.y < v1) + (q.z < v1) + (q.w < v1);
            r2 += (q.x < v2) + (q.y < v2) + (q.z < v2) + (q.w < v2);
        }
        if (r0 < SS) out[r0] = v0;
        if (r1 < SS) out[r1] = v1;
        if (64 + lane < K && r2 < SS) out[r2] = v2;
        padv = min(min(v0, v1), v2);
    } else if (K <= 128) {
        int v0 = buf[lane];
        int v1 = buf[32 + lane];
        int v2 = buf[64 + lane];
        int v3 = (96 + lane < K) ? buf[96 + lane] : 0x7fffffff;
        int r0 = 0, r1 = 0, r2 = 0, r3 = 0;
        for (int u = 0; u < nq; u++) {
            int4 q = buf4[u];
            r0 += (q.x < v0) + (q.y < v0) + (q.z < v0) + (q.w < v0);
            r1 += (q.x < v1) + (q.y < v1) + (q.z < v1) + (q.w < v1);
            r2 += (q.x < v2) + (q.y < v2) + (q.z < v2) + (q.w < v2);
            r3 += (q.x < v3) + (q.y < v3) + (q.z < v3) + (q.w < v3);
        }
        if (r0 < SS) out[r0] = v0;
        if (r1 < SS) out[r1] = v1;
        if (r2 < SS) out[r2] = v2;
        if (96 + lane < K && r3 < SS) out[r3] = v3;
        padv = min(min(v0, v1), min(v2, v3));
    } else {
        // fallback: any K up to HB
        int G = (K + 31) >> 5;
        for (int g = 0; g < G; g++) {
            int t = g * 32 + lane;
            bool val = t < K;
            int v = val ? buf[t] : 0x7fffffff;
            int r = 0;
            for (int u = 0; u < nq; u++) {
                int4 q = buf4[u];
                r += (q.x < v) + (q.y < v) + (q.z < v) + (q.w < v);
            }
            if (val && r < SS) out[r] = v;
            padv = min(padv, v);
        }
    }
#pragma unroll
    for (int o = 16; o; o >>= 1)
        padv = min(padv, __shfl_xor_sync(0xffffffffu, padv, o));
    if (K == 0) padv = 0;
    if (lane >= cnt) out[lane] = padv;       // pad with first (= min index)
}

// ---------------------------------------------------------------------------
// Grouping: one warp per query; features gathered in two 32-channel halves
// staged through a [32][33] smem tile (both phases bank-conflict-free).
// ---------------------------------------------------------------------------
__global__ void __launch_bounds__(128) group_kernel(
        const float* __restrict__ new_xyz, float* __restrict__ out) {
    __shared__ float stage[4][32][33];
    int w    = (blockIdx.x * blockDim.x + threadIdx.x) >> 5;
    int lane = threadIdx.x & 31;
    if (w >= BB * PP) return;
    int b = w / PP;
    int p = w % PP;
    float (*st)[33] = stage[(threadIdx.x >> 5) & 3];

    int i = g_idx[(size_t)w * SS + lane];

    float qx = new_xyz[3 * w + 0];
    float qy = new_xyz[3 * w + 1];
    float qz = new_xyz[3 * w + 2];

    float4 pt = g_xyz4[(size_t)b * NN + i];

    const size_t chStride = (size_t)PP * SS;
    size_t obase = (((size_t)b * CH) * PP + p) * SS + lane;

    out[obase + 0 * chStride] = pt.x - qx;
    out[obase + 1 * chStride] = pt.y - qy;
    out[obase + 2 * chStride] = pt.z - qz;

    int q = lane >> 3;            // quarter: which of 4 points this iter
    int c = lane & 7;             // 16B chunk within 128B half-row
#pragma unroll
    for (int h = 0; h < 2; h++) {           // channel halves 0..31 / 32..63
#pragma unroll
        for (int j = 0; j < 8; j++) {       // 8 iters x 4 points = 32 points
            int ptid = 4 * j + q;
            int ii = __shfl_sync(0xffffffffu, i, ptid);
            const float4* src = (const float4*)
                (g_ftrt + ((size_t)b * NN + ii) * CC + h * 32) + c;
            float4 v = *src;
            float* d = &st[ptid][c * 4];
            d[0] = v.x; d[1] = v.y; d[2] = v.z; d[3] = v.w;
        }
        __syncwarp();
        size_t fo = obase + (size_t)(3 + h * 32) * chStride;
#pragma unroll
        for (int ch = 0; ch < 32; ch++)
            out[fo + (size_t)ch * chStride] = st[lane][ch];
        __syncwarp();
    }
}

// ---------------------------------------------------------------------------
extern "C" void kernel_launch(void* const* d_in, const int* in_sizes, int n_in,
                              void* d_out, int out_size) {
    const float* xyz     = (const float*)d_in[0];   // (2,16384,3)
    const float* new_xyz = (const float*)d_in[1];   // (2,4096,3)
    const float* feat    = (const float*)d_in[2];   // (2,64,16384)
    float* out = (float*)d_out;                     // (2,67,4096,32)

    pack_count_kernel<<<(BB * NN / 4 + 255) / 256, 256>>>(xyz);
    scan_kernel<<<BB, 1024>>>();
    scatter_kernel<<<(BB * NN + 255) / 256, 256>>>();
    query_transpose_kernel<<<QBLK + TBLK, 256>>>(new_xyz, feat);
    group_kernel<<<(BB * PP) / 4, 128>>>(new_xyz, out);
}

// round 12
// speedup vs baseline: 1.5004x; 1.5004x over previous
#include <cuda_runtime.h>
#include <cuda_bf16.h>

#define BB 2
#define NN 16384
#define PP 4096
#define CC 64
#define SS 32
#define CH (3 + CC)   // 67
#define GC 10         // y,z cells (0.1)
#define GX 20         // x cells (0.05) — finer pruning granularity
#define NCELL (GC*GC*GX)   // 2000
#define HB 320        // per-warp hit buffer capacity (multiple of 4)

// ---- scratch (__device__ globals; no cudaMalloc allowed) ----
// g_cnt is zero at module load; scatter's atomicSub countdown restores it to
// zero every launch -> graph replays deterministically with no zeroing pass.
__device__ float4 g_xyz4[BB * NN];           // packed xyz, .w = cell id
__device__ float  g_ftrt[BB * NN * CC];      // features transposed to (B,N,C)
__device__ float4 g_pts [BB * NN];           // cell-sorted points, .w = idx
__device__ int    g_cnt [BB * NCELL];        // counts (self-restoring)
__device__ int    g_start[BB * (NCELL + 1)]; // exclusive scan
__device__ int    g_idx [BB * PP * SS];      // ball query result

__device__ __forceinline__ int cell_of(float x, float y, float z) {
    int cx = min((int)(x * 20.0f), GX - 1);
    int cy = min((int)(y * 10.0f), GC - 1);
    int cz = min((int)(z * 10.0f), GC - 1);
    return (cz * GC + cy) * GX + cx;
}

// ---------------------------------------------------------------------------
// Pack xyz -> float4 (+cell in .w) and histogram cells. 4 points/thread.
// ---------------------------------------------------------------------------
__global__ void pack_count_kernel(const float* __restrict__ xyz) {
    int t  = blockIdx.x * blockDim.x + threadIdx.x;
    int i0 = t * 4;
    if (i0 >= BB * NN) return;
    const float4* src = (const float4*)(xyz + (size_t)i0 * 3);
    float4 a = src[0], b4 = src[1], c4 = src[2];
    float px[4] = {a.x, a.w,  b4.z, c4.y};
    float py[4] = {a.y, b4.x, b4.w, c4.z};
    float pz[4] = {a.z, b4.y, c4.x, c4.w};
    int b = i0 / NN;
#pragma unroll
    for (int k = 0; k < 4; k++) {
        int cell = cell_of(px[k], py[k], pz[k]);
        g_xyz4[i0 + k] = make_float4(px[k], py[k], pz[k], __int_as_float(cell));
        atomicAdd(&g_cnt[b * NCELL + cell], 1);
    }
}

// ---------------------------------------------------------------------------
// Exclusive scan of 2000 counts; one block per batch; 2 cells/thread.
// Leaves g_cnt intact (scatter consumes it as a countdown).
// ---------------------------------------------------------------------------
__global__ void scan_kernel() {
    __shared__ int wsum[32];
    int b = blockIdx.x;
    int t = threadIdx.x, lane = t & 31, wid = t >> 5;
    int v0 = 0, v1 = 0;
    if (t < NCELL / 2) {
        v0 = g_cnt[b * NCELL + 2 * t];
        v1 = g_cnt[b * NCELL + 2 * t + 1];
    }
    int tv = v0 + v1;
    int s = tv;
#pragma unroll
    for (int o = 1; o < 32; o <<= 1) {
        int u = __shfl_up_sync(0xffffffffu, s, o);
        if (lane >= o) s += u;
    }
    if (lane == 31) wsum[wid] = s;
    __syncthreads();
    if (wid == 0) {
        int ws = wsum[lane];
#pragma unroll
        for (int o = 1; o < 32; o <<= 1) {
            int u = __shfl_up_sync(0xffffffffu, ws, o);
            if (lane >= o) ws += u;
        }
        wsum[lane] = ws;
    }
    __syncthreads();
    int excl = s - tv + (wid ? wsum[wid - 1] : 0);
    if (t < NCELL / 2) {
        g_start[b * (NCELL + 1) + 2 * t + 1] = excl + v0;
        g_start[b * (NCELL + 1) + 2 * t + 2] = excl + v0 + v1;
    }
    if (t == 0) g_start[b * (NCELL + 1)] = 0;
}

// ---------------------------------------------------------------------------
// Scatter into cell-sorted order; countdown atomics restore g_cnt to zero.
// ---------------------------------------------------------------------------
__global__ void scatter_kernel() {
    int i = blockIdx.x * blockDim.x + threadIdx.x;
    if (i >= BB * NN) return;
    int b = i / NN;
    float4 p = g_xyz4[i];
    int c   = __float_as_int(p.w);
    int off = atomicSub(&g_cnt[b * NCELL + c], 1) - 1;
    int pos = g_start[b * (NCELL + 1) + c] + off;
    g_pts[b * NN + pos] = make_float4(p.x, p.y, p.z, __int_as_float(i - b * NN));
}

// ---------------------------------------------------------------------------
// Fused: grid ball query (compute-bound) + feature transpose (memory-bound).
// Query: per-row x-pruned cell scan at 0.05 x-granularity (conservative
// over-include; exact frozen distance test decides). Rank: R8's proven
// all-pairs broadcast-LDS loop (every "cleverer" variant measured slower).
// ---------------------------------------------------------------------------
#define QBLK ((BB * PP) / 8)                // 1024 query blocks
#define TBLK ((NN / 32) * (CC / 32) * BB)   // 2048 transpose blocks

__global__ void __launch_bounds__(256) query_transpose_kernel(
        const float* __restrict__ new_xyz, const float* __restrict__ f) {
    __shared__ union {
        int   hb[8][HB];            // query: per-warp hit buffers
        float tile[32][33];         // transpose tile
    } sm;

    int bx = blockIdx.x;
    if (bx >= QBLK) {
        // ---- transpose part: 32ch x 32pts tile, fully vectorized ----
        int r  = bx - QBLK;
        int nt = NN / 32;
        int b  = r / (nt * 2);
        int rr = r % (nt * 2);
        int c0 = (rr / nt) * 32;
        int n0 = (rr % nt) * 32;
        int t  = threadIdx.x;
        {
            int c = t >> 3, n4 = t & 7;
            float4 v = *(const float4*)(f + ((size_t)b * CC + c0 + c) * NN
                                          + n0 + n4 * 4);
            sm.tile[c][n4 * 4 + 0] = v.x;
            sm.tile[c][n4 * 4 + 1] = v.y;
            sm.tile[c][n4 * 4 + 2] = v.z;
            sm.tile[c][n4 * 4 + 3] = v.w;
        }
        __syncthreads();
        {
            int n = t >> 3, c4 = t & 7;
            float4 v;
            v.x = sm.tile[c4 * 4 + 0][n];
            v.y = sm.tile[c4 * 4 + 1][n];
            v.z = sm.tile[c4 * 4 + 2][n];
            v.w = sm.tile[c4 * 4 + 3][n];
            *(float4*)(g_ftrt + ((size_t)b * NN + n0 + n) * CC + c0 + c4 * 4) = v;
        }
        return;
    }

    // ---- query part ----
    int w    = (bx * blockDim.x + threadIdx.x) >> 5;
    int lane = threadIdx.x & 31;
    int b = w / PP;
    int* buf = sm.hb[(threadIdx.x >> 5) & 7];

    float qx = new_xyz[3 * w + 0];
    float qy = new_xyz[3 * w + 1];
    float qz = new_xyz[3 * w + 2];
    int cy = min((int)(qy * 10.0f), GC - 1);
    int cz = min((int)(qz * 10.0f), GC - 1);

    const int*    st  = g_start + b * (NCELL + 1);
    const float4* pts = g_pts + (size_t)b * NN;

    int K = 0;
#pragma unroll
    for (int dz = -1; dz <= 1; dz++) {
        int z = cz + dz;
        if (z < 0 || z >= GC) continue;
        float dzf = (dz == 0) ? 0.0f
                  : (dz < 0 ? qz - (float)cz * 0.1f
                            : (float)(cz + 1) * 0.1f - qz);
        float dz2 = dzf * dzf;
#pragma unroll
        for (int dy = -1; dy <= 1; dy++) {
            int y = cy + dy;
            if (y < 0 || y >= GC) continue;
            float dyf = (dy == 0) ? 0.0f
                      : (dy < 0 ? qy - (float)cy * 0.1f
                                : (float)(cy + 1) * 0.1f - qy);
            float rem = 0.01f + 3e-8f - dz2 - dyf * dyf;
            if (rem <= 0.0f) continue;                 // row can't reach ball
            float dxm = __fsqrt_ru(rem);
            int x0 = max((int)((qx - dxm) * 20.0f - 1e-5f), 0);
            int x1 = min((int)((qx + dxm) * 20.0f + 1e-5f), GX - 1);
            int row = (z * GC + y) * GX;
            int rs = st[row + x0];
            int re = st[row + x1 + 1];
            for (int base = rs; base < re; base += 32) {
                int j = base + lane;
                bool hit = false; int id = 0;
                if (j < re) {
                    float4 pt = pts[j];
                    float ddx = qx - pt.x, ddy = qy - pt.y, ddz = qz - pt.z;
                    float d2 = __fmaf_rn(ddz, ddz,
                               __fmaf_rn(ddy, ddy, __fmul_rn(ddx, ddx)));
                    hit = d2 < 0.01f;
                    id  = __float_as_int(pt.w);
                }
                unsigned m = __ballot_sync(0xffffffffu, hit);
                if (hit) {
                    int pos = K + __popc(m & ((1u << lane) - 1u));
                    if (pos < HB) buf[pos] = id;
                }
                K += __popc(m);
            }
        }
    }
    if (K > HB) K = HB;
    int K4 = (K + 3) & ~3;
    if (lane < K4 - K) buf[K + lane] = 0x7fffffff;     // pad (never "smaller")
    __syncwarp();

    int* out = g_idx + (size_t)w * SS;
    int cnt  = min(K, SS);
    int padv = 0x7fffffff;
    int G = (K + 31) >> 5;
    for (int g = 0; g < G; g++) {
        int t = g * 32 + lane;
        bool val = t < K;
        int v = val ? buf[t] : 0x7fffffff;
        int r = 0;
#pragma unroll 2
        for (int u = 0; u < K4; u += 4) {    // broadcast LDS, no remainder
            int b0 = buf[u], b1 = buf[u + 1], b2 = buf[u + 2], b3 = buf[u + 3];
            r += (b0 < v) + (b1 < v) + (b2 < v) + (b3 < v);
        }
        if (val && r < SS) out[r] = v;
        padv = min(padv, v);
    }
#pragma unroll
    for (int o = 16; o; o >>= 1)
        padv = min(padv, __shfl_xor_sync(0xffffffffu, padv, o));
    if (K == 0) padv = 0;
    if (lane >= cnt) out[lane] = padv;       // pad with first (= min index)
}

// ---------------------------------------------------------------------------
// Grouping: one warp per query; features gathered in two 32-channel halves
// staged through a [32][33] smem tile (both phases bank-conflict-free).
// ---------------------------------------------------------------------------
__global__ void __launch_bounds__(128) group_kernel(
        const float* __restrict__ new_xyz, float* __restrict__ out) {
    __shared__ float stage[4][32][33];
    int w    = (blockIdx.x * blockDim.x + threadIdx.x) >> 5;
    int lane = threadIdx.x & 31;
    if (w >= BB * PP) return;
    int b = w / PP;
    int p = w % PP;
    float (*st)[33] = stage[(threadIdx.x >> 5) & 3];

    int i = g_idx[(size_t)w * SS + lane];

    float qx = new_xyz[3 * w + 0];
    float qy = new_xyz[3 * w + 1];
    float qz = new_xyz[3 * w + 2];

    float4 pt = g_xyz4[(size_t)b * NN + i];

    const size_t chStride = (size_t)PP * SS;
    size_t obase = (((size_t)b * CH) * PP + p) * SS + lane;

    out[obase + 0 * chStride] = pt.x - qx;
    out[obase + 1 * chStride] = pt.y - qy;
    out[obase + 2 * chStride] = pt.z - qz;

    int q = lane >> 3;            // quarter: which of 4 points this iter
    int c = lane & 7;             // 16B chunk within 128B half-row
#pragma unroll
    for (int h = 0; h < 2; h++) {           // channel halves 0..31 / 32..63
#pragma unroll
        for (int j = 0; j < 8; j++) {       // 8 iters x 4 points = 32 points
            int ptid = 4 * j + q;
            int ii = __shfl_sync(0xffffffffu, i, ptid);
            const float4* src = (const float4*)
                (g_ftrt + ((size_t)b * NN + ii) * CC + h * 32) + c;
            float4 v = *src;
            float* d = &st[ptid][c * 4];
            d[0] = v.x; d[1] = v.y; d[2] = v.z; d[3] = v.w;
        }
        __syncwarp();
        size_t fo = obase + (size_t)(3 + h * 32) * chStride;
#pragma unroll
        for (int ch = 0; ch < 32; ch++)
            out[fo + (size_t)ch * chStride] = st[lane][ch];
        __syncwarp();
    }
}

// ---------------------------------------------------------------------------
extern "C" void kernel_launch(void* const* d_in, const int* in_sizes, int n_in,
                              void* d_out, int out_size) {
    const float* xyz     = (const float*)d_in[0];   // (2,16384,3)
    const float* new_xyz = (const float*)d_in[1];   // (2,4096,3)
    const float* feat    = (const float*)d_in[2];   // (2,64,16384)
    float* out = (float*)d_out;                     // (2,67,4096,32)

    pack_count_kernel<<<(BB * NN / 4 + 255) / 256, 256>>>(xyz);
    scan_kernel<<<BB, 1024>>>();
    scatter_kernel<<<(BB * NN + 255) / 256, 256>>>();
    query_transpose_kernel<<<QBLK + TBLK, 256>>>(new_xyz, feat);
    group_kernel<<<(BB * PP) / 4, 128>>>(new_xyz, out);
}

// round 13
// speedup vs baseline: 1.5699x; 1.0463x over previous
#include <cuda_runtime.h>
#include <cuda_bf16.h>

#define BB 2
#define NN 16384
#define PP 4096
#define CC 64
#define SS 32
#define CH (3 + CC)   // 67
#define GC 10         // y,z cells (0.1)
#define GX 20         // x cells (0.05)
#define NCELL (GC*GC*GX)   // 2000
#define HB 320        // per-warp hit buffer capacity (multiple of 4)

// ---- scratch (__device__ globals; no cudaMalloc allowed) ----
// g_cnt/g_qcnt are zero at module load; countdown atomics restore them to
// zero every launch -> graph replays deterministically with no zeroing pass.
__device__ float4 g_xyz4[BB * NN];           // packed xyz, .w = cell id
__device__ float  g_ftrt[BB * NN * CC];      // features transposed to (B,N,C)
__device__ float4 g_pts [BB * NN];           // cell-sorted points, .w = idx
__device__ int    g_cnt [BB * NCELL];        // point counts (self-restoring)
__device__ int    g_start[BB * (NCELL + 1)]; // point scan
__device__ int    g_qcnt [BB * NCELL];       // query counts (self-restoring)
__device__ int    g_qstart[BB * (NCELL + 1)];// query scan
__device__ int    g_qcell[BB * PP];          // query cell cache
__device__ int    g_qord [BB * PP];          // cell-sorted query order
__device__ int    g_idx [BB * PP * SS];      // ball query result

__device__ __forceinline__ int cell_of(float x, float y, float z) {
    int cx = min((int)(x * 20.0f), GX - 1);
    int cy = min((int)(y * 10.0f), GC - 1);
    int cz = min((int)(z * 10.0f), GC - 1);
    return (cz * GC + cy) * GX + cx;
}

// ---------------------------------------------------------------------------
// Pack xyz -> float4 (+cell in .w), histogram point cells (4 pts/thread),
// AND histogram query cells (1 query/thread; 8192 threads == BB*PP).
// ---------------------------------------------------------------------------
__global__ void pack_count_kernel(const float* __restrict__ xyz,
                                  const float* __restrict__ new_xyz) {
    int t  = blockIdx.x * blockDim.x + threadIdx.x;
    int i0 = t * 4;
    if (i0 >= BB * NN) return;
    const float4* src = (const float4*)(xyz + (size_t)i0 * 3);
    float4 a = src[0], b4 = src[1], c4 = src[2];
    float px[4] = {a.x, a.w,  b4.z, c4.y};
    float py[4] = {a.y, b4.x, b4.w, c4.z};
    float pz[4] = {a.z, b4.y, c4.x, c4.w};
    int b = i0 / NN;
#pragma unroll
    for (int k = 0; k < 4; k++) {
        int cell = cell_of(px[k], py[k], pz[k]);
        g_xyz4[i0 + k] = make_float4(px[k], py[k], pz[k], __int_as_float(cell));
        atomicAdd(&g_cnt[b * NCELL + cell], 1);
    }
    // query histogram: thread t <-> query t (t < BB*PP == 8192)
    if (t < BB * PP) {
        int qb = t / PP;
        float qx = new_xyz[3 * t + 0];
        float qy = new_xyz[3 * t + 1];
        float qz = new_xyz[3 * t + 2];
        int qc = cell_of(qx, qy, qz);
        g_qcell[t] = qc;
        atomicAdd(&g_qcnt[qb * NCELL + qc], 1);
    }
}

// ---------------------------------------------------------------------------
// Exclusive scan of 2000 counts; grid (BB, 2): y=0 points, y=1 queries.
// Leaves counts intact (scatter consumes them as countdowns).
// ---------------------------------------------------------------------------
__global__ void scan_kernel() {
    __shared__ int wsum[32];
    int b = blockIdx.x;
    const int* cnt = (blockIdx.y == 0) ? g_cnt : g_qcnt;
    int* start     = (blockIdx.y == 0) ? g_start : g_qstart;
    int t = threadIdx.x, lane = t & 31, wid = t >> 5;
    int v0 = 0, v1 = 0;
    if (t < NCELL / 2) {
        v0 = cnt[b * NCELL + 2 * t];
        v1 = cnt[b * NCELL + 2 * t + 1];
    }
    int tv = v0 + v1;
    int s = tv;
#pragma unroll
    for (int o = 1; o < 32; o <<= 1) {
        int u = __shfl_up_sync(0xffffffffu, s, o);
        if (lane >= o) s += u;
    }
    if (lane == 31) wsum[wid] = s;
    __syncthreads();
    if (wid == 0) {
        int ws = wsum[lane];
#pragma unroll
        for (int o = 1; o < 32; o <<= 1) {
            int u = __shfl_up_sync(0xffffffffu, ws, o);
            if (lane >= o) ws += u;
        }
        wsum[lane] = ws;
    }
    __syncthreads();
    int excl = s - tv + (wid ? wsum[wid - 1] : 0);
    if (t < NCELL / 2) {
        start[b * (NCELL + 1) + 2 * t + 1] = excl + v0;
        start[b * (NCELL + 1) + 2 * t + 2] = excl + v0 + v1;
    }
    if (t == 0) start[b * (NCELL + 1)] = 0;
}

// ---------------------------------------------------------------------------
// Scatter points into cell-sorted g_pts + queries into g_qord.
// Countdown atomics restore g_cnt/g_qcnt to zero.
// ---------------------------------------------------------------------------
#define SBLK ((BB * NN) / 256)      // 128 point blocks
#define QSB  ((BB * PP) / 256)      // 32 query blocks

__global__ void scatter_kernel() {
    int bx = blockIdx.x;
    if (bx < SBLK) {
        int i = bx * 256 + threadIdx.x;
        int b = i / NN;
        float4 p = g_xyz4[i];
        int c   = __float_as_int(p.w);
        int off = atomicSub(&g_cnt[b * NCELL + c], 1) - 1;
        int pos = g_start[b * (NCELL + 1) + c] + off;
        g_pts[b * NN + pos] =
            make_float4(p.x, p.y, p.z, __int_as_float(i - b * NN));
    } else {
        int i = (bx - SBLK) * 256 + threadIdx.x;   // global query id
        int b = i / PP;
        int c = g_qcell[i];
        int off = atomicSub(&g_qcnt[b * NCELL + c], 1) - 1;
        int pos = g_qstart[b * (NCELL + 1) + c] + off;
        g_qord[b * PP + pos] = i - b * PP;         // batch-local query id
    }
}

// ---------------------------------------------------------------------------
// Fused: grid ball query (compute-bound) + feature transpose (memory-bound).
// Warps take queries in cell-sorted order (g_qord): warps in a block scan
// the same cells (L1 hits) and have similar K (load balance). Results are
// written to the ORIGINAL query slot -> output unchanged, bit-exact.
// ---------------------------------------------------------------------------
#define QBLK ((BB * PP) / 8)                // 1024 query blocks
#define TBLK ((NN / 32) * (CC / 32) * BB)   // 2048 transpose blocks

__global__ void __launch_bounds__(256) query_transpose_kernel(
        const float* __restrict__ new_xyz, const float* __restrict__ f) {
    __shared__ union {
        int   hb[8][HB];            // query: per-warp hit buffers
        float tile[32][33];         // transpose tile
    } sm;

    int bx = blockIdx.x;
    if (bx >= QBLK) {
        // ---- transpose part: 32ch x 32pts tile, fully vectorized ----
        int r  = bx - QBLK;
        int nt = NN / 32;
        int b  = r / (nt * 2);
        int rr = r % (nt * 2);
        int c0 = (rr / nt) * 32;
        int n0 = (rr % nt) * 32;
        int t  = threadIdx.x;
        {
            int c = t >> 3, n4 = t & 7;
            float4 v = *(const float4*)(f + ((size_t)b * CC + c0 + c) * NN
                                          + n0 + n4 * 4);
            sm.tile[c][n4 * 4 + 0] = v.x;
            sm.tile[c][n4 * 4 + 1] = v.y;
            sm.tile[c][n4 * 4 + 2] = v.z;
            sm.tile[c][n4 * 4 + 3] = v.w;
        }
        __syncthreads();
        {
            int n = t >> 3, c4 = t & 7;
            float4 v;
            v.x = sm.tile[c4 * 4 + 0][n];
            v.y = sm.tile[c4 * 4 + 1][n];
            v.z = sm.tile[c4 * 4 + 2][n];
            v.w = sm.tile[c4 * 4 + 3][n];
            *(float4*)(g_ftrt + ((size_t)b * NN + n0 + n) * CC + c0 + c4 * 4) = v;
        }
        return;
    }

    // ---- query part ----
    int w    = (bx * blockDim.x + threadIdx.x) >> 5;   // sorted slot
    int lane = threadIdx.x & 31;
    int b = w / PP;
    int q = g_qord[w];                                 // batch-local query id
    int gq = b * PP + q;
    int* buf = sm.hb[(threadIdx.x >> 5) & 7];

    float qx = new_xyz[3 * gq + 0];
    float qy = new_xyz[3 * gq + 1];
    float qz = new_xyz[3 * gq + 2];
    int cy = min((int)(qy * 10.0f), GC - 1);
    int cz = min((int)(qz * 10.0f), GC - 1);

    const int*    st  = g_start + b * (NCELL + 1);
    const float4* pts = g_pts + (size_t)b * NN;

    int K = 0;
#pragma unroll
    for (int dz = -1; dz <= 1; dz++) {
        int z = cz + dz;
        if (z < 0 || z >= GC) continue;
        float dzf = (dz == 0) ? 0.0f
                  : (dz < 0 ? qz - (float)cz * 0.1f
                            : (float)(cz + 1) * 0.1f - qz);
        float dz2 = dzf * dzf;
#pragma unroll
        for (int dy = -1; dy <= 1; dy++) {
            int y = cy + dy;
            if (y < 0 || y >= GC) continue;
            float dyf = (dy == 0) ? 0.0f
                      : (dy < 0 ? qy - (float)cy * 0.1f
                                : (float)(cy + 1) * 0.1f - qy);
            float rem = 0.01f + 3e-8f - dz2 - dyf * dyf;
            if (rem <= 0.0f) continue;                 // row can't reach ball
            float dxm = __fsqrt_ru(rem);
            int x0 = max((int)((qx - dxm) * 20.0f - 1e-5f), 0);
            int x1 = min((int)((qx + dxm) * 20.0f + 1e-5f), GX - 1);
            int row = (z * GC + y) * GX;
            int rs = st[row + x0];
            int re = st[row + x1 + 1];
            for (int base = rs; base < re; base += 32) {
                int j = base + lane;
                bool hit = false; int id = 0;
                if (j < re) {
                    float4 pt = pts[j];
                    float ddx = qx - pt.x, ddy = qy - pt.y, ddz = qz - pt.z;
                    float d2 = __fmaf_rn(ddz, ddz,
                               __fmaf_rn(ddy, ddy, __fmul_rn(ddx, ddx)));
                    hit = d2 < 0.01f;
                    id  = __float_as_int(pt.w);
                }
                unsigned m = __ballot_sync(0xffffffffu, hit);
                if (hit) {
                    int pos = K + __popc(m & ((1u << lane) - 1u));
                    if (pos < HB) buf[pos] = id;
                }
                K += __popc(m);
            }
        }
    }
    if (K > HB) K = HB;
    int K4 = (K + 3) & ~3;
    if (lane < K4 - K) buf[K + lane] = 0x7fffffff;     // pad (never "smaller")
    __syncwarp();

    int* out = g_idx + (size_t)gq * SS;
    int cnt  = min(K, SS);
    int padv = 0x7fffffff;
    int G = (K + 31) >> 5;
    for (int g = 0; g < G; g++) {
        int t = g * 32 + lane;
        bool val = t < K;
        int v = val ? buf[t] : 0x7fffffff;
        int r = 0;
#pragma unroll 2
        for (int u = 0; u < K4; u += 4) {    // broadcast LDS, no remainder
            int b0 = buf[u], b1 = buf[u + 1], b2 = buf[u + 2], b3 = buf[u + 3];
            r += (b0 < v) + (b1 < v) + (b2 < v) + (b3 < v);
        }
        if (val && r < SS) out[r] = v;
        padv = min(padv, v);
    }
#pragma unroll
    for (int o = 16; o; o >>= 1)
        padv = min(padv, __shfl_xor_sync(0xffffffffu, padv, o));
    if (K == 0) padv = 0;
    if (lane >= cnt) out[lane] = padv;       // pad with first (= min index)
}

// ---------------------------------------------------------------------------
// Grouping: one warp per query, taken in cell-sorted order so a block's 4
// warps gather overlapping feature rows (L1 hits). Stores go to the original
// query slot (coalesced 128B per channel as before).
// ---------------------------------------------------------------------------
__global__ void __launch_bounds__(128) group_kernel(
        const float* __restrict__ new_xyz, float* __restrict__ out) {
    __shared__ float stage[4][32][33];
    int w    = (blockIdx.x * blockDim.x + threadIdx.x) >> 5;
    int lane = threadIdx.x & 31;
    if (w >= BB * PP) return;
    int b = w / PP;
    int p = g_qord[w];                       // original (batch-local) query id
    int gq = b * PP + p;
    float (*st)[33] = stage[(threadIdx.x >> 5) & 3];

    int i = g_idx[(size_t)gq * SS + lane];

    float qx = new_xyz[3 * gq + 0];
    float qy = new_xyz[3 * gq + 1];
    float qz = new_xyz[3 * gq + 2];

    float4 pt = g_xyz4[(size_t)b * NN + i];

    const size_t chStride = (size_t)PP * SS;
    size_t obase = (((size_t)b * CH) * PP + p) * SS + lane;

    out[obase + 0 * chStride] = pt.x - qx;
    out[obase + 1 * chStride] = pt.y - qy;
    out[obase + 2 * chStride] = pt.z - qz;

    int q = lane >> 3;            // quarter: which of 4 points this iter
    int c = lane & 7;             // 16B chunk within 128B half-row
#pragma unroll
    for (int h = 0; h < 2; h++) {           // channel halves 0..31 / 32..63
#pragma unroll
        for (int j = 0; j < 8; j++) {       // 8 iters x 4 points = 32 points
            int ptid = 4 * j + q;
            int ii = __shfl_sync(0xffffffffu, i, ptid);
            const float4* src = (const float4*)
                (g_ftrt + ((size_t)b * NN + ii) * CC + h * 32) + c;
            float4 v = *src;
            float* d = &st[ptid][c * 4];
            d[0] = v.x; d[1] = v.y; d[2] = v.z; d[3] = v.w;
        }
        __syncwarp();
        size_t fo = obase + (size_t)(3 + h * 32) * chStride;
#pragma unroll
        for (int ch = 0; ch < 32; ch++)
            out[fo + (size_t)ch * chStride] = st[lane][ch];
        __syncwarp();
    }
}

// ---------------------------------------------------------------------------
extern "C" void kernel_launch(void* const* d_in, const int* in_sizes, int n_in,
                              void* d_out, int out_size) {
    const float* xyz     = (const float*)d_in[0];   // (2,16384,3)
    const float* new_xyz = (const float*)d_in[1];   // (2,4096,3)
    const float* feat    = (const float*)d_in[2];   // (2,64,16384)
    float* out = (float*)d_out;                     // (2,67,4096,32)

    pack_count_kernel<<<(BB * NN / 4 + 255) / 256, 256>>>(xyz, new_xyz);
    dim3 sg(BB, 2);
    scan_kernel<<<sg, 1024>>>();
    scatter_kernel<<<SBLK + QSB, 256>>>();
    query_transpose_kernel<<<QBLK + TBLK, 256>>>(new_xyz, feat);
    group_kernel<<<(BB * PP) / 4, 128>>>(new_xyz, out);
}